// round 13
// baseline (speedup 1.0000x reference)
#include <cuda_runtime.h>
#include <cuda_bf16.h>
#include <cstdint>

#define BATCH 32
#define NN    1024
#define NDIM  14
#define HID   64
#define HEAD  128
#define MAXD  64
#define TOTAL_NODES (BATCH * NN)   // 32768
#define GNODES 16                  // nodes per gather block
#define NPOOL (TOTAL_NODES / GNODES)   // 2048 pool partials

static_assert(TOTAL_NODES % GNODES == 0, "gather tiling");
static_assert(NN % 128 == 0, "adjacency scan tiling");

// ---------------- device scratch ----------------
__device__ int           g_nbr[TOTAL_NODES * MAXD];
__device__ int           g_cnt[TOTAL_NODES];
__device__ float         g_dinv[TOTAL_NODES];
__device__ __nv_bfloat16 g_u[TOTAL_NODES * HID];    // U = (prescaled h) @ W
__device__ __nv_bfloat16 g_h[TOTAL_NODES * HID];    // activations (prescaled by dinv)
__device__ float         g_pool[NPOOL * HID];       // fp32 partial pools

// ---------------- 1) adjacency scan (float4, warp per row) ----------------
__global__ void build_edges_kernel(const float* __restrict__ adj) {
    int row  = blockIdx.x * 8 + (threadIdx.x >> 5);
    int lane = threadIdx.x & 31;
    if (row >= TOTAL_NODES) return;

    const float4* arow = (const float4*)(adj + (size_t)row * NN);
    int* nl = &g_nbr[(size_t)row * MAXD];
    int cnt = 0;
    const unsigned lt = (1u << lane) - 1u;

    #pragma unroll
    for (int s = 0; s < NN / 128; s++) {           // 8 iterations
        float4 v = arow[s * 32 + lane];
        bool b0 = v.x > 0.5f, b1 = v.y > 0.5f, b2 = v.z > 0.5f, b3 = v.w > 0.5f;
        unsigned m0 = __ballot_sync(0xffffffffu, b0);
        unsigned m1 = __ballot_sync(0xffffffffu, b1);
        unsigned m2 = __ballot_sync(0xffffffffu, b2);
        unsigned m3 = __ballot_sync(0xffffffffu, b3);
        int prior = __popc(m0 & lt) + __popc(m1 & lt) + __popc(m2 & lt) + __popc(m3 & lt);
        int colbase = s * 128 + lane * 4;
        int p = cnt + prior;
        if (b0) { if (p < MAXD) nl[p] = colbase + 0; p++; }
        if (b1) { if (p < MAXD) nl[p] = colbase + 1; p++; }
        if (b2) { if (p < MAXD) nl[p] = colbase + 2; p++; }
        if (b3) { if (p < MAXD) nl[p] = colbase + 3; }
        cnt += __popc(m0) + __popc(m1) + __popc(m2) + __popc(m3);
    }
    if (lane == 0) {
        g_cnt[row]  = cnt < MAXD ? cnt : MAXD;
        g_dinv[row] = rsqrtf((float)cnt);
    }
}

// ---------------- helpers ----------------
__device__ __forceinline__ void acc_bf16x8(uint4 raw, float* acc) {
    float2 f;
    f = __bfloat1622float2(*reinterpret_cast<__nv_bfloat162*>(&raw.x)); acc[0] += f.x; acc[1] += f.y;
    f = __bfloat1622float2(*reinterpret_cast<__nv_bfloat162*>(&raw.y)); acc[2] += f.x; acc[3] += f.y;
    f = __bfloat1622float2(*reinterpret_cast<__nv_bfloat162*>(&raw.z)); acc[4] += f.x; acc[5] += f.y;
    f = __bfloat1622float2(*reinterpret_cast<__nv_bfloat162*>(&raw.w)); acc[6] += f.x; acc[7] += f.y;
}

__device__ __forceinline__ void gather_node(const __nv_bfloat16* __restrict__ in,
                                            const int* __restrict__ nl, int cnt,
                                            int bbase, int lane8, float* acc) {
    #pragma unroll
    for (int q = 0; q < 8; q++) acc[q] = 0.0f;
    int j = 0;
    for (; j + 4 <= cnt; j += 4) {
        const int4 idx = *(const int4*)&nl[j];
        uint4 r0 = *(const uint4*)(in + (size_t)(bbase + idx.x) * 64 + lane8 * 8);
        uint4 r1 = *(const uint4*)(in + (size_t)(bbase + idx.y) * 64 + lane8 * 8);
        uint4 r2 = *(const uint4*)(in + (size_t)(bbase + idx.z) * 64 + lane8 * 8);
        uint4 r3 = *(const uint4*)(in + (size_t)(bbase + idx.w) * 64 + lane8 * 8);
        acc_bf16x8(r0, acc); acc_bf16x8(r1, acc);
        acc_bf16x8(r2, acc); acc_bf16x8(r3, acc);
    }
    if (j + 2 <= cnt) {
        const int j0 = nl[j], j1 = nl[j + 1];
        uint4 r0 = *(const uint4*)(in + (size_t)(bbase + j0) * 64 + lane8 * 8);
        uint4 r1 = *(const uint4*)(in + (size_t)(bbase + j1) * 64 + lane8 * 8);
        acc_bf16x8(r0, acc); acc_bf16x8(r1, acc);
        j += 2;
    }
    if (j < cnt) {
        uint4 r0 = *(const uint4*)(in + (size_t)(bbase + nl[j]) * 64 + lane8 * 8);
        acc_bf16x8(r0, acc);
    }
}

__device__ __forceinline__ void st_bf16x8(__nv_bfloat16* p, const float* v) {
    union { __nv_bfloat162 h2[4]; uint4 u; } cvt;
    cvt.h2[0] = __floats2bfloat162_rn(v[0], v[1]);
    cvt.h2[1] = __floats2bfloat162_rn(v[2], v[3]);
    cvt.h2[2] = __floats2bfloat162_rn(v[4], v[5]);
    cvt.h2[3] = __floats2bfloat162_rn(v[6], v[7]);
    *(uint4*)p = cvt.u;
}

// ---------------- 2) U1 = dinv_j * (x_j @ W1), bf16 out ----------------
__global__ __launch_bounds__(128)
void xw_kernel(const float* __restrict__ x,
               const float* __restrict__ W1,
               __nv_bfloat16* __restrict__ out) {
    __shared__ float Ws[NDIM][64];
    const int tid = threadIdx.x;
    for (int i = tid; i < NDIM * 64; i += 128) Ws[i >> 6][i & 63] = W1[i];
    __syncthreads();

    const int grp  = tid >> 4;       // 0..7
    const int lane = tid & 15;       // 0..15
    const int node = blockIdx.x * 8 + grp;

    float xv[NDIM];
    #pragma unroll
    for (int k = 0; k < NDIM; k++) xv[k] = x[(size_t)node * NDIM + k];

    float o[4] = {0.f, 0.f, 0.f, 0.f};
    #pragma unroll
    for (int k = 0; k < NDIM; k++) {
        const float4 w = *(const float4*)&Ws[k][lane * 4];
        o[0] = fmaf(xv[k], w.x, o[0]);
        o[1] = fmaf(xv[k], w.y, o[1]);
        o[2] = fmaf(xv[k], w.z, o[2]);
        o[3] = fmaf(xv[k], w.w, o[3]);
    }
    const float d = g_dinv[node];
    union { __nv_bfloat162 h2[2]; uint2 u; } cvt;
    cvt.h2[0] = __floats2bfloat162_rn(o[0] * d, o[1] * d);
    cvt.h2[1] = __floats2bfloat162_rn(o[2] * d, o[3] * d);
    *(uint2*)&out[(size_t)node * 64 + lane * 4] = cvt.u;
}

// ---------------- 3) dense GEMM: U[32768,64] = h[32768,64] @ W[64,64] --------
// 256 threads, 64 rows/block, grid 512. bf16 in, fp32 accumulate, bf16 out.
__global__ __launch_bounds__(256)
void gemm64_kernel(const __nv_bfloat16* __restrict__ A,
                   const float* __restrict__ W,
                   __nv_bfloat16* __restrict__ U) {
    __shared__ float As[64][68];
    __shared__ float Ws[64][64];
    const int tid = threadIdx.x;
    const size_t rowBase = (size_t)blockIdx.x * 64;

    #pragma unroll
    for (int i = tid; i < 1024; i += 256)
        ((float4*)Ws)[i] = ((const float4*)W)[i];

    #pragma unroll
    for (int i = tid; i < 512; i += 256) {
        const int r = i >> 3, c8 = i & 7;
        uint4 raw = *(const uint4*)(A + (rowBase + r) * 64 + c8 * 8);
        float2 f;
        float* dst = &As[r][c8 * 8];
        f = __bfloat1622float2(*reinterpret_cast<__nv_bfloat162*>(&raw.x)); dst[0] = f.x; dst[1] = f.y;
        f = __bfloat1622float2(*reinterpret_cast<__nv_bfloat162*>(&raw.y)); dst[2] = f.x; dst[3] = f.y;
        f = __bfloat1622float2(*reinterpret_cast<__nv_bfloat162*>(&raw.z)); dst[4] = f.x; dst[5] = f.y;
        f = __bfloat1622float2(*reinterpret_cast<__nv_bfloat162*>(&raw.w)); dst[6] = f.x; dst[7] = f.y;
    }
    __syncthreads();

    const int tx = tid & 15;    // 4 cols each
    const int ty = tid >> 4;    // 4 rows each
    float c[4][4];
    #pragma unroll
    for (int i = 0; i < 4; i++)
        #pragma unroll
        for (int j = 0; j < 4; j++) c[i][j] = 0.0f;

    #pragma unroll
    for (int kk = 0; kk < 64; kk += 4) {
        float4 a[4], b[4];
        #pragma unroll
        for (int i = 0; i < 4; i++) a[i] = *(const float4*)&As[ty * 4 + i][kk];
        #pragma unroll
        for (int q = 0; q < 4; q++) b[q] = *(const float4*)&Ws[kk + q][tx * 4];
        #pragma unroll
        for (int i = 0; i < 4; i++) {
            const float ai[4] = {a[i].x, a[i].y, a[i].z, a[i].w};
            #pragma unroll
            for (int q = 0; q < 4; q++) {
                c[i][0] = fmaf(ai[q], b[q].x, c[i][0]);
                c[i][1] = fmaf(ai[q], b[q].y, c[i][1]);
                c[i][2] = fmaf(ai[q], b[q].z, c[i][2]);
                c[i][3] = fmaf(ai[q], b[q].w, c[i][3]);
            }
        }
    }

    #pragma unroll
    for (int i = 0; i < 4; i++) {
        union { __nv_bfloat162 h2[2]; uint2 u; } cvt;
        cvt.h2[0] = __floats2bfloat162_rn(c[i][0], c[i][1]);
        cvt.h2[1] = __floats2bfloat162_rn(c[i][2], c[i][3]);
        *(uint2*)&U[(rowBase + ty * 4 + i) * 64 + tx * 4] = cvt.u;
    }
}

// ---------------- 4) pure gather + bias + relu (no shared, no syncs) --------
// in = U (pre-scaled by dinv_j). out_i = dinv_i * relu(dinv_i*sum + b).
// 128 threads, 8 lanes/node -> 16 nodes/block, grid 2048.
__global__ __launch_bounds__(128)
void gather_relu_kernel(const __nv_bfloat16* __restrict__ in,
                        const float* __restrict__ bias,
                        __nv_bfloat16* __restrict__ out) {
    const int tid   = threadIdx.x;
    const int grp   = tid >> 3;      // 0..15
    const int lane  = tid & 7;       // 0..7
    const int node  = blockIdx.x * GNODES + grp;
    const int bbase = node & ~(NN - 1);

    float acc[8];
    gather_node(in, &g_nbr[(size_t)node * MAXD], g_cnt[node], bbase, lane, acc);

    const float di = g_dinv[node];
    const float4 b0 = *(const float4*)&bias[lane * 8];
    const float4 b1 = *(const float4*)&bias[lane * 8 + 4];
    float o[8];
    o[0] = fmaxf(fmaf(di, acc[0], b0.x), 0.f) * di;
    o[1] = fmaxf(fmaf(di, acc[1], b0.y), 0.f) * di;
    o[2] = fmaxf(fmaf(di, acc[2], b0.z), 0.f) * di;
    o[3] = fmaxf(fmaf(di, acc[3], b0.w), 0.f) * di;
    o[4] = fmaxf(fmaf(di, acc[4], b1.x), 0.f) * di;
    o[5] = fmaxf(fmaf(di, acc[5], b1.y), 0.f) * di;
    o[6] = fmaxf(fmaf(di, acc[6], b1.z), 0.f) * di;
    o[7] = fmaxf(fmaf(di, acc[7], b1.w), 0.f) * di;
    st_bf16x8(&out[(size_t)node * 64 + lane * 8], o);
}

// ---------------- 5) final gather + bias + relu + block pool ----------------
// relu (unscaled) summed over the block's 16 nodes -> g_pool[blockIdx].
__global__ __launch_bounds__(128)
void gather_pool_kernel(const __nv_bfloat16* __restrict__ in,
                        const float* __restrict__ bias) {
    __shared__ float red[GNODES][66];
    const int tid   = threadIdx.x;
    const int grp   = tid >> 3;      // 0..15
    const int lane  = tid & 7;       // 0..7
    const int node  = blockIdx.x * GNODES + grp;
    const int bbase = node & ~(NN - 1);

    float acc[8];
    gather_node(in, &g_nbr[(size_t)node * MAXD], g_cnt[node], bbase, lane, acc);

    const float di = g_dinv[node];
    const float4 b0 = *(const float4*)&bias[lane * 8];
    const float4 b1 = *(const float4*)&bias[lane * 8 + 4];
    float* dst = &red[grp][lane * 8];
    dst[0] = fmaxf(fmaf(di, acc[0], b0.x), 0.f);
    dst[1] = fmaxf(fmaf(di, acc[1], b0.y), 0.f);
    dst[2] = fmaxf(fmaf(di, acc[2], b0.z), 0.f);
    dst[3] = fmaxf(fmaf(di, acc[3], b0.w), 0.f);
    dst[4] = fmaxf(fmaf(di, acc[4], b1.x), 0.f);
    dst[5] = fmaxf(fmaf(di, acc[5], b1.y), 0.f);
    dst[6] = fmaxf(fmaf(di, acc[6], b1.z), 0.f);
    dst[7] = fmaxf(fmaf(di, acc[7], b1.w), 0.f);
    __syncthreads();

    if (tid < 64) {
        float s = 0.0f;
        #pragma unroll
        for (int r = 0; r < GNODES; r++) s += red[r][tid];
        g_pool[(size_t)blockIdx.x * HID + tid] = s;
    }
}

// ---------------- 6) head: combine partials + MLP ----------------
__global__ void head_kernel(const float* __restrict__ Wf1,
                            const float* __restrict__ bf1,
                            const float* __restrict__ Wf2,
                            const float* __restrict__ bf2,
                            float* __restrict__ out) {
    const int b = blockIdx.x, tid = threadIdx.x;
    const int chunks = NN / GNODES;   // 64 partials per batch
    __shared__ float pooled[64];
    __shared__ float red[128];

    if (tid < 64) {
        float s = 0.0f;
        #pragma unroll
        for (int c = 0; c < chunks; c++) s += g_pool[(b * chunks + c) * HID + tid];
        pooled[tid] = s * (1.0f / (float)NN);
    }
    __syncthreads();

    float a = bf1[tid];
    #pragma unroll
    for (int kk = 0; kk < 64; kk++) a = fmaf(pooled[kk], Wf1[kk * HEAD + tid], a);
    red[tid] = fmaxf(a, 0.0f) * Wf2[tid];
    __syncthreads();
    for (int off = 64; off > 0; off >>= 1) {
        if (tid < off) red[tid] += red[tid + off];
        __syncthreads();
    }
    if (tid == 0) out[b] = red[0] + bf2[0];
}

// ---------------- launch ----------------
extern "C" void kernel_launch(void* const* d_in, const int* in_sizes, int n_in,
                              void* d_out, int out_size) {
    const float* x   = (const float*)d_in[0];
    const float* adj = (const float*)d_in[1];
    const float* W1  = (const float*)d_in[2];
    const float* b1  = (const float*)d_in[3];
    const float* W2  = (const float*)d_in[4];
    const float* b2  = (const float*)d_in[5];
    const float* W3  = (const float*)d_in[6];
    const float* b3  = (const float*)d_in[7];
    const float* Wf1 = (const float*)d_in[8];
    const float* bf1 = (const float*)d_in[9];
    const float* Wf2 = (const float*)d_in[10];
    const float* bf2 = (const float*)d_in[11];
    float* out = (float*)d_out;

    __nv_bfloat16 *u, *h;
    cudaGetSymbolAddress((void**)&u, g_u);
    cudaGetSymbolAddress((void**)&h, g_h);

    build_edges_kernel<<<TOTAL_NODES / 8, 256>>>(adj);
    xw_kernel<<<TOTAL_NODES / 8, 128>>>(x, W1, u);                 // U1 = dinv*(x@W1)
    gather_relu_kernel<<<TOTAL_NODES / GNODES, 128>>>(u, b1, h);   // h1 (prescaled)
    gemm64_kernel<<<TOTAL_NODES / 64, 256>>>(h, W2, u);            // U2 = h1@W2
    gather_relu_kernel<<<TOTAL_NODES / GNODES, 128>>>(u, b2, h);   // h2 (prescaled)
    gemm64_kernel<<<TOTAL_NODES / 64, 256>>>(h, W3, u);            // U3 = h2@W3
    gather_pool_kernel<<<TOTAL_NODES / GNODES, 128>>>(u, b3);      // pool partials
    head_kernel<<<BATCH, 128>>>(Wf1, bf1, Wf2, bf2, out);
}

// round 14
// speedup vs baseline: 1.1042x; 1.1042x over previous
#include <cuda_runtime.h>
#include <cuda_bf16.h>
#include <cstdint>

#define BATCH 32
#define NN    1024
#define NDIM  14
#define HID   64
#define HEAD  128
#define MAXD  64
#define TOTAL_NODES (BATCH * NN)   // 32768
#define NODES_PER_BLK 32
#define NBLK (TOTAL_NODES / NODES_PER_BLK)   // 1024
#define GNODES 16

static_assert(TOTAL_NODES % NODES_PER_BLK == 0, "block tiling");
static_assert(NN % 128 == 0, "adjacency scan tiling");

// ---------------- device scratch (activation buffers have +1 zero row) ------
__device__ int           g_nbr[TOTAL_NODES * MAXD];   // ABSOLUTE indices, padded w/ sentinel
__device__ int           g_cnt[TOTAL_NODES];          // padded counts (multiple of 4)
__device__ float         g_dinv[TOTAL_NODES];
__device__ __nv_bfloat16 g_xw[(TOTAL_NODES + 1) * HID];
__device__ __nv_bfloat16 g_h1[(TOTAL_NODES + 1) * HID];
__device__ __nv_bfloat16 g_h2[(TOTAL_NODES + 1) * HID];
__device__ float         g_pool[NBLK * HID];

// ---------------- 1) adjacency scan (float4, warp per row) ----------------
// Stores ABSOLUTE neighbor indices; pads to a multiple of 4 with sentinel
// TOTAL_NODES (an always-zero row in every activation buffer).
// Block 0 also zeroes the three sentinel rows.
__global__ void build_edges_kernel(const float* __restrict__ adj) {
    if (blockIdx.x == 0 && threadIdx.x < 96) {
        // zero rows: 64 bf16 = 32 u32 per buffer, 3 buffers
        const int t = threadIdx.x;
        uint32_t* dst;
        if (t < 32)       dst = (uint32_t*)&g_xw[(size_t)TOTAL_NODES * HID] + t;
        else if (t < 64)  dst = (uint32_t*)&g_h1[(size_t)TOTAL_NODES * HID] + (t - 32);
        else              dst = (uint32_t*)&g_h2[(size_t)TOTAL_NODES * HID] + (t - 64);
        *dst = 0u;
    }

    int row  = blockIdx.x * 8 + (threadIdx.x >> 5);
    int lane = threadIdx.x & 31;
    if (row >= TOTAL_NODES) return;

    const int bbase = row & ~(NN - 1);
    const float4* arow = (const float4*)(adj + (size_t)row * NN);
    int* nl = &g_nbr[(size_t)row * MAXD];
    int cnt = 0;
    const unsigned lt = (1u << lane) - 1u;

    #pragma unroll
    for (int s = 0; s < NN / 128; s++) {           // 8 iterations
        float4 v = arow[s * 32 + lane];
        bool b0 = v.x > 0.5f, b1 = v.y > 0.5f, b2 = v.z > 0.5f, b3 = v.w > 0.5f;
        unsigned m0 = __ballot_sync(0xffffffffu, b0);
        unsigned m1 = __ballot_sync(0xffffffffu, b1);
        unsigned m2 = __ballot_sync(0xffffffffu, b2);
        unsigned m3 = __ballot_sync(0xffffffffu, b3);
        int prior = __popc(m0 & lt) + __popc(m1 & lt) + __popc(m2 & lt) + __popc(m3 & lt);
        int colbase = bbase + s * 128 + lane * 4;
        int p = cnt + prior;
        if (b0) { if (p < MAXD) nl[p] = colbase + 0; p++; }
        if (b1) { if (p < MAXD) nl[p] = colbase + 1; p++; }
        if (b2) { if (p < MAXD) nl[p] = colbase + 2; p++; }
        if (b3) { if (p < MAXD) nl[p] = colbase + 3; }
        cnt += __popc(m0) + __popc(m1) + __popc(m2) + __popc(m3);
    }
    if (lane == 0) {
        const int c      = cnt < MAXD ? cnt : MAXD;
        int padded       = (c + 3) & ~3;
        if (padded > MAXD) padded = MAXD;
        for (int t = c; t < padded; t++) nl[t] = TOTAL_NODES;   // sentinel
        g_cnt[row]  = padded;
        g_dinv[row] = rsqrtf((float)cnt);
    }
}

// ---------------- helpers ----------------
__device__ __forceinline__ void acc_bf16x8(uint4 raw, float* acc) {
    float2 f;
    f = __bfloat1622float2(*reinterpret_cast<__nv_bfloat162*>(&raw.x)); acc[0] += f.x; acc[1] += f.y;
    f = __bfloat1622float2(*reinterpret_cast<__nv_bfloat162*>(&raw.y)); acc[2] += f.x; acc[3] += f.y;
    f = __bfloat1622float2(*reinterpret_cast<__nv_bfloat162*>(&raw.z)); acc[4] += f.x; acc[5] += f.y;
    f = __bfloat1622float2(*reinterpret_cast<__nv_bfloat162*>(&raw.w)); acc[6] += f.x; acc[7] += f.y;
}

// uniform guard-free gather: cntp is a multiple of 4, indices are absolute
__device__ __forceinline__ void gather_node(const __nv_bfloat16* __restrict__ in,
                                            const int* __restrict__ nl, int cntp,
                                            int lane8, float* acc) {
    #pragma unroll
    for (int q = 0; q < 8; q++) acc[q] = 0.0f;
    #pragma unroll 2
    for (int j = 0; j < cntp; j += 4) {
        const int4 idx = *(const int4*)&nl[j];
        uint4 r0 = *(const uint4*)(in + (size_t)idx.x * 64 + lane8 * 8);
        uint4 r1 = *(const uint4*)(in + (size_t)idx.y * 64 + lane8 * 8);
        uint4 r2 = *(const uint4*)(in + (size_t)idx.z * 64 + lane8 * 8);
        uint4 r3 = *(const uint4*)(in + (size_t)idx.w * 64 + lane8 * 8);
        acc_bf16x8(r0, acc); acc_bf16x8(r1, acc);
        acc_bf16x8(r2, acc); acc_bf16x8(r3, acc);
    }
}

__device__ __forceinline__ void st_bf16x8(__nv_bfloat16* p, const float* v) {
    union { __nv_bfloat162 h2[4]; uint4 u; } cvt;
    cvt.h2[0] = __floats2bfloat162_rn(v[0], v[1]);
    cvt.h2[1] = __floats2bfloat162_rn(v[2], v[3]);
    cvt.h2[2] = __floats2bfloat162_rn(v[4], v[5]);
    cvt.h2[3] = __floats2bfloat162_rn(v[6], v[7]);
    *(uint4*)p = cvt.u;
}

// ---------------- 2) U1 = dinv_j * (x_j @ W1), bf16 out ----------------
__global__ __launch_bounds__(128)
void xw_kernel(const float* __restrict__ x,
               const float* __restrict__ W1,
               __nv_bfloat16* __restrict__ out) {
    __shared__ float Ws[NDIM][64];
    const int tid = threadIdx.x;
    for (int i = tid; i < NDIM * 64; i += 128) Ws[i >> 6][i & 63] = W1[i];
    __syncthreads();

    const int grp  = tid >> 4;       // 0..7
    const int lane = tid & 15;       // 0..15
    const int node = blockIdx.x * 8 + grp;

    float xv[NDIM];
    #pragma unroll
    for (int k = 0; k < NDIM; k++) xv[k] = x[(size_t)node * NDIM + k];

    float o[4] = {0.f, 0.f, 0.f, 0.f};
    #pragma unroll
    for (int k = 0; k < NDIM; k++) {
        const float4 w = *(const float4*)&Ws[k][lane * 4];
        o[0] = fmaf(xv[k], w.x, o[0]);
        o[1] = fmaf(xv[k], w.y, o[1]);
        o[2] = fmaf(xv[k], w.z, o[2]);
        o[3] = fmaf(xv[k], w.w, o[3]);
    }
    const float d = g_dinv[node];
    union { __nv_bfloat162 h2[2]; uint2 u; } cvt;
    cvt.h2[0] = __floats2bfloat162_rn(o[0] * d, o[1] * d);
    cvt.h2[1] = __floats2bfloat162_rn(o[2] * d, o[3] * d);
    *(uint2*)&out[(size_t)node * 64 + lane * 4] = cvt.u;
}

// ---------------- 3) layer 1: pure gather + bias + relu ----------------
// in = U1 (pre-scaled). out_i = dinv_i * relu(dinv_i*sum + b1).
__global__ __launch_bounds__(128)
void gather_relu_kernel(const __nv_bfloat16* __restrict__ in,
                        const float* __restrict__ bias,
                        __nv_bfloat16* __restrict__ out) {
    const int tid  = threadIdx.x;
    const int grp  = tid >> 3;       // 0..15
    const int lane = tid & 7;        // 0..7
    const int node = blockIdx.x * GNODES + grp;

    float acc[8];
    gather_node(in, &g_nbr[(size_t)node * MAXD], g_cnt[node], lane, acc);

    const float di = g_dinv[node];
    const float4 b0 = *(const float4*)&bias[lane * 8];
    const float4 b1 = *(const float4*)&bias[lane * 8 + 4];
    float o[8];
    o[0] = fmaxf(fmaf(di, acc[0], b0.x), 0.f) * di;
    o[1] = fmaxf(fmaf(di, acc[1], b0.y), 0.f) * di;
    o[2] = fmaxf(fmaf(di, acc[2], b0.z), 0.f) * di;
    o[3] = fmaxf(fmaf(di, acc[3], b0.w), 0.f) * di;
    o[4] = fmaxf(fmaf(di, acc[4], b1.x), 0.f) * di;
    o[5] = fmaxf(fmaf(di, acc[5], b1.y), 0.f) * di;
    o[6] = fmaxf(fmaf(di, acc[6], b1.z), 0.f) * di;
    o[7] = fmaxf(fmaf(di, acc[7], b1.w), 0.f) * di;
    st_bf16x8(&out[(size_t)node * 64 + lane * 8], o);
}

// ---------------- 4) layers 2/3: fused gather + GEMM + bias + relu ---------
// 128 threads, 32 nodes/block.
template <bool SCALE_OUT, bool POOL>
__global__ __launch_bounds__(128)
void gcn_layer_kernel(const __nv_bfloat16* __restrict__ in,
                      const float* __restrict__ W,
                      const float* __restrict__ bias,
                      __nv_bfloat16* __restrict__ out) {
    __shared__ float Ag[NODES_PER_BLK][68];
    __shared__ float Ws[64][64];
    __shared__ float bs[64];

    const int tid       = threadIdx.x;
    const int blockBase = blockIdx.x * NODES_PER_BLK;

    #pragma unroll
    for (int i = tid; i < 64 * 16; i += 128)
        ((float4*)Ws)[i] = ((const float4*)W)[i];
    if (tid < 64) bs[tid] = bias[tid];

    // ---- Phase A: gather (uniform loop, absolute indices) ----
    {
        const int grp  = tid >> 3;   // 0..15
        const int lane = tid & 7;    // 0..7
        #pragma unroll
        for (int s = 0; s < 2; s++) {
            const int n    = grp * 2 + s;
            const int node = blockBase + n;
            float acc[8];
            gather_node(in, &g_nbr[(size_t)node * MAXD], g_cnt[node], lane, acc);
            const float di = g_dinv[node];
            float4 lo = make_float4(acc[0] * di, acc[1] * di, acc[2] * di, acc[3] * di);
            float4 hi = make_float4(acc[4] * di, acc[5] * di, acc[6] * di, acc[7] * di);
            *(float4*)&Ag[n][lane * 8]     = lo;
            *(float4*)&Ag[n][lane * 8 + 4] = hi;
        }
    }
    __syncthreads();

    // ---- Phase B: [32 x 64] @ [64 x 64], 4x4 microtiles ----
    {
        const int tx = tid & 15;
        const int ty = tid >> 4;
        float c[4][4];
        #pragma unroll
        for (int i = 0; i < 4; i++)
            #pragma unroll
            for (int j = 0; j < 4; j++) c[i][j] = 0.0f;

        #pragma unroll
        for (int kk = 0; kk < 64; kk += 4) {
            float4 a[4], b[4];
            #pragma unroll
            for (int i = 0; i < 4; i++) a[i] = *(const float4*)&Ag[ty * 4 + i][kk];
            #pragma unroll
            for (int q = 0; q < 4; q++) b[q] = *(const float4*)&Ws[kk + q][tx * 4];
            #pragma unroll
            for (int i = 0; i < 4; i++) {
                const float ai[4] = {a[i].x, a[i].y, a[i].z, a[i].w};
                #pragma unroll
                for (int q = 0; q < 4; q++) {
                    c[i][0] = fmaf(ai[q], b[q].x, c[i][0]);
                    c[i][1] = fmaf(ai[q], b[q].y, c[i][1]);
                    c[i][2] = fmaf(ai[q], b[q].z, c[i][2]);
                    c[i][3] = fmaf(ai[q], b[q].w, c[i][3]);
                }
            }
        }

        float colsum[4] = {0.f, 0.f, 0.f, 0.f};
        #pragma unroll
        for (int i = 0; i < 4; i++) {
            const int row = blockBase + ty * 4 + i;
            float4 o;
            o.x = fmaxf(c[i][0] + bs[tx * 4 + 0], 0.0f);
            o.y = fmaxf(c[i][1] + bs[tx * 4 + 1], 0.0f);
            o.z = fmaxf(c[i][2] + bs[tx * 4 + 2], 0.0f);
            o.w = fmaxf(c[i][3] + bs[tx * 4 + 3], 0.0f);
            if (POOL) {
                colsum[0] += o.x; colsum[1] += o.y;
                colsum[2] += o.z; colsum[3] += o.w;
            } else {
                const float dscale = SCALE_OUT ? g_dinv[row] : 1.0f;
                union { __nv_bfloat162 h2[2]; uint2 u; } cvt;
                cvt.h2[0] = __floats2bfloat162_rn(o.x * dscale, o.y * dscale);
                cvt.h2[1] = __floats2bfloat162_rn(o.z * dscale, o.w * dscale);
                *(uint2*)&out[(size_t)row * 64 + tx * 4] = cvt.u;
            }
        }

        if (POOL) {
            __syncthreads();               // done reading Ag; reuse it
            #pragma unroll
            for (int q = 0; q < 4; q++) Ag[ty][tx * 4 + q] = colsum[q];
            __syncthreads();
            if (tid < 64) {
                float s = 0.0f;
                #pragma unroll
                for (int r = 0; r < 8; r++) s += Ag[r][tid];
                g_pool[blockIdx.x * HID + tid] = s;
            }
        }
    }
}

// ---------------- 5) head: combine partials + MLP ----------------
__global__ void head_kernel(const float* __restrict__ Wf1,
                            const float* __restrict__ bf1,
                            const float* __restrict__ Wf2,
                            const float* __restrict__ bf2,
                            float* __restrict__ out) {
    const int b = blockIdx.x, tid = threadIdx.x;
    const int chunks = NN / NODES_PER_BLK;   // 32 partials per batch
    __shared__ float pooled[64];
    __shared__ float red[128];

    if (tid < 64) {
        float s = 0.0f;
        #pragma unroll
        for (int c = 0; c < chunks; c++) s += g_pool[(b * chunks + c) * HID + tid];
        pooled[tid] = s * (1.0f / (float)NN);
    }
    __syncthreads();

    float a = bf1[tid];
    #pragma unroll
    for (int kk = 0; kk < 64; kk++) a = fmaf(pooled[kk], Wf1[kk * HEAD + tid], a);
    red[tid] = fmaxf(a, 0.0f) * Wf2[tid];
    __syncthreads();
    for (int off = 64; off > 0; off >>= 1) {
        if (tid < off) red[tid] += red[tid + off];
        __syncthreads();
    }
    if (tid == 0) out[b] = red[0] + bf2[0];
}

// ---------------- launch ----------------
extern "C" void kernel_launch(void* const* d_in, const int* in_sizes, int n_in,
                              void* d_out, int out_size) {
    const float* x   = (const float*)d_in[0];
    const float* adj = (const float*)d_in[1];
    const float* W1  = (const float*)d_in[2];
    const float* b1  = (const float*)d_in[3];
    const float* W2  = (const float*)d_in[4];
    const float* b2  = (const float*)d_in[5];
    const float* W3  = (const float*)d_in[6];
    const float* b3  = (const float*)d_in[7];
    const float* Wf1 = (const float*)d_in[8];
    const float* bf1 = (const float*)d_in[9];
    const float* Wf2 = (const float*)d_in[10];
    const float* bf2 = (const float*)d_in[11];
    float* out = (float*)d_out;

    __nv_bfloat16 *xw, *h1, *h2;
    cudaGetSymbolAddress((void**)&xw, g_xw);
    cudaGetSymbolAddress((void**)&h1, g_h1);
    cudaGetSymbolAddress((void**)&h2, g_h2);

    build_edges_kernel<<<TOTAL_NODES / 8, 256>>>(adj);
    xw_kernel<<<TOTAL_NODES / 8, 128>>>(x, W1, xw);                // U1 = dinv*(x@W1)
    gather_relu_kernel<<<TOTAL_NODES / GNODES, 128>>>(xw, b1, h1); // h1 (prescaled)
    gcn_layer_kernel<true,  false><<<NBLK, 128>>>(h1, W2, b2, h2); // h2 (prescaled)
    gcn_layer_kernel<false, true ><<<NBLK, 128>>>(h2, W3, b3, h1); // pool partials
    head_kernel<<<BATCH, 128>>>(Wf1, bf1, Wf2, bf2, out);
}

// round 16
// speedup vs baseline: 1.1732x; 1.0625x over previous
#include <cuda_runtime.h>
#include <cuda_bf16.h>
#include <cstdint>

#define BATCH 32
#define NN    1024
#define NDIM  14
#define HID   64
#define HEAD  128
#define MAXD  64
#define TOTAL_NODES (BATCH * NN)   // 32768
#define NODES_PER_BLK 32
#define NBLK (TOTAL_NODES / NODES_PER_BLK)   // 1024
#define GNODES 16

static_assert(TOTAL_NODES % NODES_PER_BLK == 0, "block tiling");
static_assert(NN % 128 == 0, "adjacency scan tiling");

// ---------------- device scratch (activation buffers have +1 zero row) ------
__device__ int           g_nbr[TOTAL_NODES * MAXD];   // ABSOLUTE indices, padded w/ sentinel
__device__ int           g_cnt[TOTAL_NODES];          // padded counts (multiple of 4)
__device__ float         g_dinv[TOTAL_NODES];
__device__ __nv_bfloat16 g_xw[(TOTAL_NODES + 1) * HID];
__device__ __nv_bfloat16 g_h1[(TOTAL_NODES + 1) * HID];
__device__ __nv_bfloat16 g_h2[(TOTAL_NODES + 1) * HID];
__device__ float         g_pool[NBLK * HID];

// ---------------- 1) adjacency scan (float4, warp per row) ----------------
__global__ void build_edges_kernel(const float* __restrict__ adj) {
    if (blockIdx.x == 0 && threadIdx.x < 96) {
        const int t = threadIdx.x;
        uint32_t* dst;
        if (t < 32)       dst = (uint32_t*)&g_xw[(size_t)TOTAL_NODES * HID] + t;
        else if (t < 64)  dst = (uint32_t*)&g_h1[(size_t)TOTAL_NODES * HID] + (t - 32);
        else              dst = (uint32_t*)&g_h2[(size_t)TOTAL_NODES * HID] + (t - 64);
        *dst = 0u;
    }

    int row  = blockIdx.x * 8 + (threadIdx.x >> 5);
    int lane = threadIdx.x & 31;
    if (row >= TOTAL_NODES) return;

    const int bbase = row & ~(NN - 1);
    const float4* arow = (const float4*)(adj + (size_t)row * NN);
    int* nl = &g_nbr[(size_t)row * MAXD];
    int cnt = 0;
    const unsigned lt = (1u << lane) - 1u;

    #pragma unroll
    for (int s = 0; s < NN / 128; s++) {           // 8 iterations
        float4 v = arow[s * 32 + lane];
        bool b0 = v.x > 0.5f, b1 = v.y > 0.5f, b2 = v.z > 0.5f, b3 = v.w > 0.5f;
        unsigned m0 = __ballot_sync(0xffffffffu, b0);
        unsigned m1 = __ballot_sync(0xffffffffu, b1);
        unsigned m2 = __ballot_sync(0xffffffffu, b2);
        unsigned m3 = __ballot_sync(0xffffffffu, b3);
        int prior = __popc(m0 & lt) + __popc(m1 & lt) + __popc(m2 & lt) + __popc(m3 & lt);
        int colbase = bbase + s * 128 + lane * 4;
        int p = cnt + prior;
        if (b0) { if (p < MAXD) nl[p] = colbase + 0; p++; }
        if (b1) { if (p < MAXD) nl[p] = colbase + 1; p++; }
        if (b2) { if (p < MAXD) nl[p] = colbase + 2; p++; }
        if (b3) { if (p < MAXD) nl[p] = colbase + 3; }
        cnt += __popc(m0) + __popc(m1) + __popc(m2) + __popc(m3);
    }
    if (lane == 0) {
        const int c      = cnt < MAXD ? cnt : MAXD;
        int padded       = (c + 3) & ~3;
        if (padded > MAXD) padded = MAXD;
        for (int t = c; t < padded; t++) nl[t] = TOTAL_NODES;   // sentinel
        g_cnt[row]  = padded;
        g_dinv[row] = rsqrtf((float)cnt);
    }
}

// ---------------- helpers ----------------
__device__ __forceinline__ void acc_bf16x8(uint4 raw, float* acc) {
    float2 f;
    f = __bfloat1622float2(*reinterpret_cast<__nv_bfloat162*>(&raw.x)); acc[0] += f.x; acc[1] += f.y;
    f = __bfloat1622float2(*reinterpret_cast<__nv_bfloat162*>(&raw.y)); acc[2] += f.x; acc[3] += f.y;
    f = __bfloat1622float2(*reinterpret_cast<__nv_bfloat162*>(&raw.z)); acc[4] += f.x; acc[5] += f.y;
    f = __bfloat1622float2(*reinterpret_cast<__nv_bfloat162*>(&raw.w)); acc[6] += f.x; acc[7] += f.y;
}

__device__ __forceinline__ void gather_node(const __nv_bfloat16* __restrict__ in,
                                            const int* __restrict__ nl, int cntp,
                                            int lane8, float* acc) {
    #pragma unroll
    for (int q = 0; q < 8; q++) acc[q] = 0.0f;
    #pragma unroll 2
    for (int j = 0; j < cntp; j += 4) {
        const int4 idx = *(const int4*)&nl[j];
        uint4 r0 = *(const uint4*)(in + (size_t)idx.x * 64 + lane8 * 8);
        uint4 r1 = *(const uint4*)(in + (size_t)idx.y * 64 + lane8 * 8);
        uint4 r2 = *(const uint4*)(in + (size_t)idx.z * 64 + lane8 * 8);
        uint4 r3 = *(const uint4*)(in + (size_t)idx.w * 64 + lane8 * 8);
        acc_bf16x8(r0, acc); acc_bf16x8(r1, acc);
        acc_bf16x8(r2, acc); acc_bf16x8(r3, acc);
    }
}

__device__ __forceinline__ void st_bf16x8(__nv_bfloat16* p, const float* v) {
    union { __nv_bfloat162 h2[4]; uint4 u; } cvt;
    cvt.h2[0] = __floats2bfloat162_rn(v[0], v[1]);
    cvt.h2[1] = __floats2bfloat162_rn(v[2], v[3]);
    cvt.h2[2] = __floats2bfloat162_rn(v[4], v[5]);
    cvt.h2[3] = __floats2bfloat162_rn(v[6], v[7]);
    *(uint4*)p = cvt.u;
}

__device__ __forceinline__ uint32_t f2tf32(float x) {
    uint32_t r;
    asm("cvt.rna.tf32.f32 %0, %1;" : "=r"(r) : "f"(x));
    return r;
}

__device__ __forceinline__ void mma_tf32(float* c, const uint32_t* a, const uint32_t* b) {
    asm volatile(
        "mma.sync.aligned.m16n8k8.row.col.f32.tf32.tf32.f32 "
        "{%0,%1,%2,%3}, {%4,%5,%6,%7}, {%8,%9}, {%0,%1,%2,%3};"
        : "+f"(c[0]), "+f"(c[1]), "+f"(c[2]), "+f"(c[3])
        : "r"(a[0]), "r"(a[1]), "r"(a[2]), "r"(a[3]), "r"(b[0]), "r"(b[1]));
}

// ---------------- 2) U1 = dinv_j * (x_j @ W1), bf16 out ----------------
__global__ __launch_bounds__(128)
void xw_kernel(const float* __restrict__ x,
               const float* __restrict__ W1,
               __nv_bfloat16* __restrict__ out) {
    __shared__ float Ws[NDIM][64];
    const int tid = threadIdx.x;
    for (int i = tid; i < NDIM * 64; i += 128) Ws[i >> 6][i & 63] = W1[i];
    __syncthreads();

    const int grp  = tid >> 4;
    const int lane = tid & 15;
    const int node = blockIdx.x * 8 + grp;

    float xv[NDIM];
    #pragma unroll
    for (int k = 0; k < NDIM; k++) xv[k] = x[(size_t)node * NDIM + k];

    float o[4] = {0.f, 0.f, 0.f, 0.f};
    #pragma unroll
    for (int k = 0; k < NDIM; k++) {
        const float4 w = *(const float4*)&Ws[k][lane * 4];
        o[0] = fmaf(xv[k], w.x, o[0]);
        o[1] = fmaf(xv[k], w.y, o[1]);
        o[2] = fmaf(xv[k], w.z, o[2]);
        o[3] = fmaf(xv[k], w.w, o[3]);
    }
    const float d = g_dinv[node];
    union { __nv_bfloat162 h2[2]; uint2 u; } cvt;
    cvt.h2[0] = __floats2bfloat162_rn(o[0] * d, o[1] * d);
    cvt.h2[1] = __floats2bfloat162_rn(o[2] * d, o[3] * d);
    *(uint2*)&out[(size_t)node * 64 + lane * 4] = cvt.u;
}

// ---------------- 3) layer 1: pure gather + bias + relu ----------------
__global__ __launch_bounds__(128)
void gather_relu_kernel(const __nv_bfloat16* __restrict__ in,
                        const float* __restrict__ bias,
                        __nv_bfloat16* __restrict__ out) {
    const int tid  = threadIdx.x;
    const int grp  = tid >> 3;
    const int lane = tid & 7;
    const int node = blockIdx.x * GNODES + grp;

    float acc[8];
    gather_node(in, &g_nbr[(size_t)node * MAXD], g_cnt[node], lane, acc);

    const float di = g_dinv[node];
    const float4 b0 = *(const float4*)&bias[lane * 8];
    const float4 b1 = *(const float4*)&bias[lane * 8 + 4];
    float o[8];
    o[0] = fmaxf(fmaf(di, acc[0], b0.x), 0.f) * di;
    o[1] = fmaxf(fmaf(di, acc[1], b0.y), 0.f) * di;
    o[2] = fmaxf(fmaf(di, acc[2], b0.z), 0.f) * di;
    o[3] = fmaxf(fmaf(di, acc[3], b0.w), 0.f) * di;
    o[4] = fmaxf(fmaf(di, acc[4], b1.x), 0.f) * di;
    o[5] = fmaxf(fmaf(di, acc[5], b1.y), 0.f) * di;
    o[6] = fmaxf(fmaf(di, acc[6], b1.z), 0.f) * di;
    o[7] = fmaxf(fmaf(di, acc[7], b1.w), 0.f) * di;
    st_bf16x8(&out[(size_t)node * 64 + lane * 8], o);
}

// ---------------- 4) layers 2/3: fused gather + tf32-MMA GEMM ---------------
// 128 threads (4 warps), 32 nodes/block. Phase B: mma.sync.m16n8k8.tf32,
// warp w owns output columns [16w, 16w+16). A and W are tf32-rounded.
template <bool SCALE_OUT, bool POOL>
__global__ __launch_bounds__(128)
void gcn_layer_kernel(const __nv_bfloat16* __restrict__ in,
                      const float* __restrict__ W,
                      const float* __restrict__ bias,
                      __nv_bfloat16* __restrict__ out) {
    __shared__ float Ag[NODES_PER_BLK][68];   // gathered tile (tf32-rounded)
    __shared__ float Ws[64][68];              // weights (tf32-rounded)
    __shared__ float bs[64];

    const int tid       = threadIdx.x;
    const int blockBase = blockIdx.x * NODES_PER_BLK;

    // stage W with tf32 rounding
    #pragma unroll
    for (int i = tid; i < 1024; i += 128) {     // 64*64/4 float4 chunks
        const float4 w = ((const float4*)W)[i];
        const int r = i >> 4, c = (i & 15) * 4;
        float4 t;
        t.x = __uint_as_float(f2tf32(w.x));
        t.y = __uint_as_float(f2tf32(w.y));
        t.z = __uint_as_float(f2tf32(w.z));
        t.w = __uint_as_float(f2tf32(w.w));
        *(float4*)&Ws[r][c] = t;
    }
    if (tid < 64) bs[tid] = bias[tid];

    // ---- Phase A: gather (uniform loop, absolute indices) ----
    {
        const int grp  = tid >> 3;   // 0..15
        const int lane = tid & 7;    // 0..7
        #pragma unroll
        for (int s = 0; s < 2; s++) {
            const int n    = grp * 2 + s;
            const int node = blockBase + n;
            float acc[8];
            gather_node(in, &g_nbr[(size_t)node * MAXD], g_cnt[node], lane, acc);
            const float di = g_dinv[node];
            float4 lo, hi;
            lo.x = __uint_as_float(f2tf32(acc[0] * di));
            lo.y = __uint_as_float(f2tf32(acc[1] * di));
            lo.z = __uint_as_float(f2tf32(acc[2] * di));
            lo.w = __uint_as_float(f2tf32(acc[3] * di));
            hi.x = __uint_as_float(f2tf32(acc[4] * di));
            hi.y = __uint_as_float(f2tf32(acc[5] * di));
            hi.z = __uint_as_float(f2tf32(acc[6] * di));
            hi.w = __uint_as_float(f2tf32(acc[7] * di));
            *(float4*)&Ag[n][lane * 8]     = lo;
            *(float4*)&Ag[n][lane * 8 + 4] = hi;
        }
    }
    __syncthreads();

    // ---- Phase B: [32 x 64] @ [64 x 64] via mma.m16n8k8.tf32 ----
    {
        const int warpId = tid >> 5;
        const int lane   = tid & 31;
        const int gid    = lane >> 2;    // 0..7
        const int tig    = lane & 3;     // 0..3
        const int nbase  = warpId * 16;

        float c[2][2][4];
        #pragma unroll
        for (int m = 0; m < 2; m++)
            #pragma unroll
            for (int n = 0; n < 2; n++)
                #pragma unroll
                for (int q = 0; q < 4; q++) c[m][n][q] = 0.0f;

        #pragma unroll
        for (int k8 = 0; k8 < 64; k8 += 8) {
            uint32_t a[2][4], b[2][2];
            #pragma unroll
            for (int m = 0; m < 2; m++) {
                const int r0 = m * 16 + gid;
                a[m][0] = __float_as_uint(Ag[r0][k8 + tig]);
                a[m][1] = __float_as_uint(Ag[r0 + 8][k8 + tig]);
                a[m][2] = __float_as_uint(Ag[r0][k8 + tig + 4]);
                a[m][3] = __float_as_uint(Ag[r0 + 8][k8 + tig + 4]);
            }
            #pragma unroll
            for (int n = 0; n < 2; n++) {
                b[n][0] = __float_as_uint(Ws[k8 + tig][nbase + n * 8 + gid]);
                b[n][1] = __float_as_uint(Ws[k8 + tig + 4][nbase + n * 8 + gid]);
            }
            #pragma unroll
            for (int m = 0; m < 2; m++)
                #pragma unroll
                for (int n = 0; n < 2; n++)
                    mma_tf32(c[m][n], a[m], b[n]);
        }

        // ---- epilogue ----
        if (!POOL) {
            #pragma unroll
            for (int m = 0; m < 2; m++) {
                #pragma unroll
                for (int half = 0; half < 2; half++) {
                    const int row = blockBase + m * 16 + gid + half * 8;
                    const float dscale = SCALE_OUT ? g_dinv[row] : 1.0f;
                    #pragma unroll
                    for (int n = 0; n < 2; n++) {
                        const int col = nbase + n * 8 + tig * 2;
                        const float v0 = fmaxf(c[m][n][half * 2 + 0] + bs[col], 0.0f) * dscale;
                        const float v1 = fmaxf(c[m][n][half * 2 + 1] + bs[col + 1], 0.0f) * dscale;
                        __nv_bfloat162 pk = __floats2bfloat162_rn(v0, v1);
                        *(__nv_bfloat162*)&out[(size_t)row * 64 + col] = pk;
                    }
                }
            }
        } else {
            // column sums of relu over all 32 rows of this block
            float s[2][2];   // [n][col in pair]
            #pragma unroll
            for (int n = 0; n < 2; n++) {
                const int col = nbase + n * 8 + tig * 2;
                const float bc0 = bs[col], bc1 = bs[col + 1];
                float s0 = 0.f, s1 = 0.f;
                #pragma unroll
                for (int m = 0; m < 2; m++) {
                    s0 += fmaxf(c[m][n][0] + bc0, 0.f) + fmaxf(c[m][n][2] + bc0, 0.f);
                    s1 += fmaxf(c[m][n][1] + bc1, 0.f) + fmaxf(c[m][n][3] + bc1, 0.f);
                }
                s[n][0] = s0; s[n][1] = s1;
            }
            #pragma unroll
            for (int n = 0; n < 2; n++)
                #pragma unroll
                for (int p = 0; p < 2; p++) {
                    s[n][p] += __shfl_xor_sync(0xffffffffu, s[n][p], 4);
                    s[n][p] += __shfl_xor_sync(0xffffffffu, s[n][p], 8);
                    s[n][p] += __shfl_xor_sync(0xffffffffu, s[n][p], 16);
                }
            if (gid == 0) {
                #pragma unroll
                for (int n = 0; n < 2; n++) {
                    const int col = nbase + n * 8 + tig * 2;
                    g_pool[(size_t)blockIdx.x * HID + col]     = s[n][0];
                    g_pool[(size_t)blockIdx.x * HID + col + 1] = s[n][1];
                }
            }
        }
    }
}

// ---------------- 5) head: combine partials + MLP ----------------
__global__ void head_kernel(const float* __restrict__ Wf1,
                            const float* __restrict__ bf1,
                            const float* __restrict__ Wf2,
                            const float* __restrict__ bf2,
                            float* __restrict__ out) {
    const int b = blockIdx.x, tid = threadIdx.x;
    const int chunks = NN / NODES_PER_BLK;   // 32 partials per batch
    __shared__ float pooled[64];
    __shared__ float red[128];

    if (tid < 64) {
        float s = 0.0f;
        #pragma unroll
        for (int c = 0; c < chunks; c++) s += g_pool[(b * chunks + c) * HID + tid];
        pooled[tid] = s * (1.0f / (float)NN);
    }
    __syncthreads();

    float a = bf1[tid];
    #pragma unroll
    for (int kk = 0; kk < 64; kk++) a = fmaf(pooled[kk], Wf1[kk * HEAD + tid], a);
    red[tid] = fmaxf(a, 0.0f) * Wf2[tid];
    __syncthreads();
    for (int off = 64; off > 0; off >>= 1) {
        if (tid < off) red[tid] += red[tid + off];
        __syncthreads();
    }
    if (tid == 0) out[b] = red[0] + bf2[0];
}

// ---------------- launch ----------------
extern "C" void kernel_launch(void* const* d_in, const int* in_sizes, int n_in,
                              void* d_out, int out_size) {
    const float* x   = (const float*)d_in[0];
    const float* adj = (const float*)d_in[1];
    const float* W1  = (const float*)d_in[2];
    const float* b1  = (const float*)d_in[3];
    const float* W2  = (const float*)d_in[4];
    const float* b2  = (const float*)d_in[5];
    const float* W3  = (const float*)d_in[6];
    const float* b3  = (const float*)d_in[7];
    const float* Wf1 = (const float*)d_in[8];
    const float* bf1 = (const float*)d_in[9];
    const float* Wf2 = (const float*)d_in[10];
    const float* bf2 = (const float*)d_in[11];
    float* out = (float*)d_out;

    __nv_bfloat16 *xw, *h1, *h2;
    cudaGetSymbolAddress((void**)&xw, g_xw);
    cudaGetSymbolAddress((void**)&h1, g_h1);
    cudaGetSymbolAddress((void**)&h2, g_h2);

    build_edges_kernel<<<TOTAL_NODES / 8, 256>>>(adj);
    xw_kernel<<<TOTAL_NODES / 8, 128>>>(x, W1, xw);                // U1 = dinv*(x@W1)
    gather_relu_kernel<<<TOTAL_NODES / GNODES, 128>>>(xw, b1, h1); // h1 (prescaled)
    gcn_layer_kernel<true,  false><<<NBLK, 128>>>(h1, W2, b2, h2); // h2 (prescaled)
    gcn_layer_kernel<false, true ><<<NBLK, 128>>>(h2, W3, b3, h1); // pool partials
    head_kernel<<<BATCH, 128>>>(Wf1, bf1, Wf2, bf2, out);
}